// round 10
// baseline (speedup 1.0000x reference)
#include <cuda_runtime.h>
#include <math.h>

#define S_LEN 4096
#define HID 2304
#define NH 8
#define NKV 4
#define HD 256
#define QDIM 2048
#define KVDIM 1024
#define SWIN 2048
#define ATTN_SCALE 0.0625f

__device__ float g_q [S_LEN*QDIM];
__device__ float g_k [S_LEN*KVDIM];
__device__ float g_v [S_LEN*KVDIM];
__device__ float g_vt[KVDIM*S_LEN];
__device__ float g_ao[S_LEN*QDIM];
__device__ float g_x [S_LEN*HID];
__device__ float g_wq[QDIM*HID];
__device__ float g_wk[KVDIM*HID];
__device__ float g_wv[KVDIM*HID];
__device__ float g_wo[HID*QDIM];

__device__ __forceinline__ unsigned f2tf(float f) {
    unsigned u; asm("cvt.rna.tf32.f32 %0, %1;" : "=r"(u) : "f"(f)); return u;
}
__device__ __forceinline__ unsigned s2u(const void* p) {
    return (unsigned)__cvta_generic_to_shared(p);
}
__device__ __forceinline__ void ldsm4(unsigned& r0, unsigned& r1, unsigned& r2, unsigned& r3, unsigned a) {
    asm volatile("ldmatrix.sync.aligned.m8n8.x4.shared.b16 {%0,%1,%2,%3},[%4];"
                 : "=r"(r0), "=r"(r1), "=r"(r2), "=r"(r3) : "r"(a));
}
__device__ __forceinline__ void cpa16(unsigned d, const float* s) {
    asm volatile("cp.async.cg.shared.global [%0],[%1],16;" :: "r"(d), "l"(s));
}
#define CP_COMMIT() asm volatile("cp.async.commit_group;")
#define CP_WAIT0()  asm volatile("cp.async.wait_group 0;")
#define CP_WAIT1()  asm volatile("cp.async.wait_group 1;")

__device__ __forceinline__ void mma_tf32(float& c0, float& c1, float& c2, float& c3,
        unsigned a0, unsigned a1, unsigned a2, unsigned a3, unsigned b0, unsigned b1) {
    asm volatile("mma.sync.aligned.m16n8k8.row.col.f32.tf32.tf32.f32 "
        "{%0,%1,%2,%3},{%4,%5,%6,%7},{%8,%9},{%0,%1,%2,%3};\n"
        : "+f"(c0), "+f"(c1), "+f"(c2), "+f"(c3)
        : "r"(a0), "r"(a1), "r"(a2), "r"(a3), "r"(b0), "r"(b1));
}

__global__ __launch_bounds__(256) void round_copy(float* __restrict__ d, const float* __restrict__ s, int n4) {
    int i = blockIdx.x * 256 + threadIdx.x;
    if (i < n4) {
        float4 v = ((const float4*)s)[i];
        ((uint4*)d)[i] = make_uint4(f2tf(v.x), f2tf(v.y), f2tf(v.z), f2tf(v.w));
    }
}

// round all four weights in one launch.
// wq: 1179648 f4, wk/wv: 589824 f4 each, wo: 1179648 f4. total 3538944 f4.
__global__ __launch_bounds__(256) void round_w4(const float* __restrict__ wq,
        const float* __restrict__ wk, const float* __restrict__ wv,
        const float* __restrict__ wo) {
    int i = blockIdx.x * 256 + threadIdx.x;
    const float* s; float* d; int off;
    if (i < 1179648)      { s = wq; d = g_wq; off = i; }
    else if (i < 1769472) { s = wk; d = g_wk; off = i - 1179648; }
    else if (i < 2359296) { s = wv; d = g_wv; off = i - 1769472; }
    else                  { s = wo; d = g_wo; off = i - 2359296; }
    float4 v = ((const float4*)s)[off];
    ((uint4*)d)[off] = make_uint4(f2tf(v.x), f2tf(v.y), f2tf(v.z), f2tf(v.w));
}

__global__ __launch_bounds__(256) void transpose_round_v() {
    __shared__ float tile[32][33];
    int s0 = blockIdx.x * 32, d0 = blockIdx.y * 32;
    int tx = threadIdx.x & 31, ty = threadIdx.x >> 5;
#pragma unroll
    for (int i = 0; i < 4; i++)
        tile[ty + 8*i][tx] = g_v[(size_t)(s0 + ty + 8*i) * KVDIM + d0 + tx];
    __syncthreads();
#pragma unroll
    for (int i = 0; i < 4; i++)
        g_vt[(size_t)(d0 + ty + 8*i) * S_LEN + s0 + tx] = __uint_as_float(f2tf(tile[tx][ty + 8*i]));
}

__global__ __launch_bounds__(256) void rope_kernel(const int* __restrict__ pos) {
    __shared__ float cs[128], sn[128];
    const int s = blockIdx.x, t = threadIdx.x;
    const float p = (float)pos[s];
    if (t < 128) {
        float invf = 1.0f / powf(10000.0f, (float)(2 * t) / 256.0f);
        sincosf(p * invf, &sn[t], &cs[t]);
    }
    __syncthreads();
    for (int idx = t; idx < (NH + NKV) * 128; idx += 256) {
        int h = idx >> 7, d = idx & 127;
        float c = cs[d], ss = sn[d];
        float* b = (h < NH) ? (g_q + (size_t)s * QDIM + h * HD)
                            : (g_k + (size_t)s * KVDIM + (h - NH) * HD);
        float x1 = b[d], x2 = b[d + 128];
        b[d]       = __uint_as_float(f2tf(x1 * c - x2 * ss));
        b[d + 128] = __uint_as_float(f2tf(x2 * c + x1 * ss));
    }
}

// ---------------- GEMM core (128 thr, 128x128 tile, 3-stage cp.async) ------
#define GKP 36
__device__ __forceinline__ void g3_issue(unsigned sa, unsigned sb,
        const float* __restrict__ A, const float* __restrict__ B,
        int m0, int bn0, int K, int k0, int r0w, int cw) {
#pragma unroll
    for (int i = 0; i < 8; i++) {
        int r = r0w + 16 * i;
        cpa16(sa + (unsigned)((r * GKP + cw) * 4), A + (size_t)(m0 + r) * K + k0 + cw);
        cpa16(sb + (unsigned)((r * GKP + cw) * 4), B + (size_t)(bn0 + r) * K + k0 + cw);
    }
    CP_COMMIT();
}

// QKV==1: fused projection with output routing; QKV==0: plain C=A*B^T
template<int QKV>
__global__ __launch_bounds__(128) void gemm3(const float* __restrict__ A,
        const float* __restrict__ B_, float* __restrict__ C_, int N, int K) {
    extern __shared__ float smf[];
    const int t = threadIdx.x, lane = t & 31, wid = t >> 5;
    const int g = lane >> 2, tig = lane & 3;
    const int wm = (wid >> 1) * 64, wn = (wid & 1) * 64;
    const int m0 = blockIdx.y * 128, n0 = blockIdx.x * 128;
    const unsigned sb0 = s2u(smf);
    const unsigned STG = 128u * GKP * 4u;
    const int r0w = t >> 3, cw = (t & 7) * 4;
    const int lrow = (lane & 7) + ((lane >> 4) & 1) * 8;
    const int lcol = ((lane >> 3) & 1) * 4;

    const float* B; float* C; int bn0, Nld;
    if (QKV) {
        if (n0 < 2048)      { B = g_wq; C = g_q; bn0 = n0;        Nld = 2048; }
        else if (n0 < 3072) { B = g_wk; C = g_k; bn0 = n0 - 2048; Nld = 1024; }
        else                { B = g_wv; C = g_v; bn0 = n0 - 3072; Nld = 1024; }
    } else { B = B_; C = C_; bn0 = n0; Nld = N; }

    float acc[4][8][4];
#pragma unroll
    for (int mt = 0; mt < 4; mt++)
#pragma unroll
        for (int nt = 0; nt < 8; nt++)
#pragma unroll
            for (int c = 0; c < 4; c++) acc[mt][nt][c] = 0.f;

    const int nch = K >> 5;
    g3_issue(sb0, sb0 + 3u*STG, A, B, m0, bn0, K, 0, r0w, cw);
    g3_issue(sb0 + STG, sb0 + 4u*STG, A, B, m0, bn0, K, 32, r0w, cw);
    for (int ci = 0; ci < nch; ci++) {
        if (ci + 1 < nch) { CP_WAIT1(); } else { CP_WAIT0(); }
        __syncthreads();
        if (ci + 2 < nch) {
            int s = (ci + 2) % 3;
            g3_issue(sb0 + (unsigned)s*STG, sb0 + (unsigned)(s+3)*STG, A, B, m0, bn0, K, (ci + 2) << 5, r0w, cw);
        }
        const unsigned sa = sb0 + (unsigned)(ci % 3) * STG;
        const unsigned sbb = sb0 + (unsigned)(ci % 3 + 3) * STG;
#pragma unroll
        for (int ks = 0; ks < 32; ks += 8) {
            unsigned a[4][4], b[4][4];
#pragma unroll
            for (int mt = 0; mt < 4; mt++)
                ldsm4(a[mt][0], a[mt][1], a[mt][2], a[mt][3],
                      sa + (unsigned)(((wm + mt*16 + lrow) * GKP + ks + lcol) * 4));
#pragma unroll
            for (int p = 0; p < 4; p++)
                ldsm4(b[p][0], b[p][1], b[p][2], b[p][3],
                      sbb + (unsigned)(((wn + p*16 + lrow) * GKP + ks + lcol) * 4));
#pragma unroll
            for (int nt = 0; nt < 8; nt++) {
                unsigned b0 = b[nt >> 1][(nt & 1) * 2], b1 = b[nt >> 1][(nt & 1) * 2 + 1];
#pragma unroll
                for (int mt = 0; mt < 4; mt++)
                    mma_tf32(acc[mt][nt][0], acc[mt][nt][1], acc[mt][nt][2], acc[mt][nt][3],
                             a[mt][0], a[mt][2], a[mt][1], a[mt][3], b0, b1);
            }
        }
    }
#pragma unroll
    for (int mt = 0; mt < 4; mt++) {
        int row = m0 + wm + mt * 16 + g;
#pragma unroll
        for (int nt = 0; nt < 8; nt++) {
            int col = bn0 + wn + nt * 8 + 2 * tig;
            *(float2*)&C[(size_t)row * Nld + col]       = make_float2(acc[mt][nt][0], acc[mt][nt][1]);
            *(float2*)&C[(size_t)(row + 8) * Nld + col] = make_float2(acc[mt][nt][2], acc[mt][nt][3]);
        }
    }
}

// ---------------- Flash attention: 8 warps, split-HD warp pairs -------------
#define BQ 64
#define BK 32
#define AQP 260
#define AVP 36
#define SXOFF (64*AQP + 2*32*AQP + 2*256*AVP)   // 51712 words

__device__ __forceinline__ void attn_issue(unsigned sk, unsigned sv, int j0, int hkv, int t) {
#pragma unroll
    for (int i = 0; i < 8; i++) {
        int c = t + 256 * i;
        int r = c >> 6, col = (c & 63) * 4;
        cpa16(sk + (unsigned)((r * AQP + col) * 4), g_k + (size_t)(j0 + r) * KVDIM + hkv * HD + col);
    }
#pragma unroll
    for (int i = 0; i < 8; i++) {
        int c = t + 256 * i;
        int r = c >> 3, col = (c & 7) * 4;
        cpa16(sv + (unsigned)((r * AVP + col) * 4), g_vt + (size_t)(hkv * HD + r) * S_LEN + j0 + col);
    }
    CP_COMMIT();
}

__global__ __launch_bounds__(256, 1) void attn_tc(float* __restrict__ out) {
    extern __shared__ float smf[];
    const unsigned sb0 = s2u(smf);
    const unsigned sQ  = sb0;
    const unsigned sK0 = sb0 + 64u*AQP*4u, sK1 = sK0 + 32u*AQP*4u;
    const unsigned sV0 = sK1 + 32u*AQP*4u, sV1 = sV0 + 256u*AVP*4u;
    float* Qs = smf;
    float* Sx = smf + SXOFF;   // 8 warps x 512 words exchange

    const int t = threadIdx.x, lane = t & 31, wid = t >> 5;
    const int g = lane >> 2, tig = lane & 3;
    const int pairid = wid & 3, half = wid >> 2;
    const int h = blockIdx.y;
    const int q0 = (int)(gridDim.x - 1 - blockIdx.x) * BQ;
    const int hkv = h >> 1;
    const int rbase = pairid * 16;
    const int ksbase = half * 128;
    const int qi_lo = q0 + rbase + g, qi_hi = qi_lo + 8;
    const int lrow = (lane & 7) + ((lane >> 4) & 1) * 8;
    const int lcol = ((lane >> 3) & 1) * 4;
    float* myS   = Sx + wid * 512;
    float* peerS = Sx + (wid ^ 4) * 512;

    int jlo = q0 - (SWIN - 1); if (jlo < 0) jlo = 0;
    const int jstart = jlo & ~(BK - 1);
    const int ntiles = (q0 + BQ - jstart) / BK;

    attn_issue(sK0, sV0, jstart, hkv, t);
    for (int i = t; i < 64 * 64; i += 256) {
        int r = i >> 6, c = (i & 63) * 4;
        *(float4*)&Qs[r * AQP + c] = *(const float4*)&g_q[(size_t)(q0 + r) * QDIM + h * HD + c];
    }
    __syncthreads();

    // hoist Q fragments into registers (tile-invariant): 16 k-steps x 4 regs
    unsigned qa[16][4];
#pragma unroll
    for (int ksi = 0; ksi < 16; ksi++)
        ldsm4(qa[ksi][0], qa[ksi][1], qa[ksi][2], qa[ksi][3],
              sQ + (unsigned)(((rbase + lrow) * AQP + ksbase + ksi * 8 + lcol) * 4));

    float o[16][4];
#pragma unroll
    for (int nt = 0; nt < 16; nt++)
#pragma unroll
        for (int c = 0; c < 4; c++) o[nt][c] = 0.f;
    float m_lo = -1e30f, m_hi = -1e30f, l_lo = 0.f, l_hi = 0.f;

    for (int ci = 0; ci < ntiles; ci++) {
        const int j0 = jstart + ci * BK;
        CP_WAIT0();
        __syncthreads();
        if (ci + 1 < ntiles)
            attn_issue((ci & 1) ? sK0 : sK1, (ci & 1) ? sV0 : sV1, j0 + BK, hkv, t);
        const unsigned sk = (ci & 1) ? sK1 : sK0;
        const unsigned sv = (ci & 1) ? sV1 : sV0;

        // ---- QK^T over this warp's half of HD (Q from registers) ----
        float sc[4][4];
#pragma unroll
        for (int nt = 0; nt < 4; nt++)
#pragma unroll
            for (int c = 0; c < 4; c++) sc[nt][c] = 0.f;
#pragma unroll 4
        for (int ksi = 0; ksi < 16; ksi++) {
            unsigned kb[2][4];
#pragma unroll
            for (int p = 0; p < 2; p++)
                ldsm4(kb[p][0], kb[p][1], kb[p][2], kb[p][3],
                      sk + (unsigned)(((p * 16 + lrow) * AQP + ksbase + ksi * 8 + lcol) * 4));
#pragma unroll
            for (int nt = 0; nt < 4; nt++) {
                unsigned b0 = kb[nt >> 1][(nt & 1) * 2], b1 = kb[nt >> 1][(nt & 1) * 2 + 1];
                mma_tf32(sc[nt][0], sc[nt][1], sc[nt][2], sc[nt][3],
                         qa[ksi][0], qa[ksi][2], qa[ksi][1], qa[ksi][3], b0, b1);
            }
        }

        // ---- exchange partial scores with pair warp (named pair barrier) ----
#pragma unroll
        for (int nt = 0; nt < 4; nt++)
#pragma unroll
            for (int c = 0; c < 4; c++)
                myS[(nt * 4 + c) * 32 + lane] = sc[nt][c];
        asm volatile("bar.sync %0, 64;" :: "r"(pairid + 1));
#pragma unroll
        for (int nt = 0; nt < 4; nt++)
#pragma unroll
            for (int c = 0; c < 4; c++)
                sc[nt][c] += peerS[(nt * 4 + c) * 32 + lane];

        // ---- softcap + mask + online softmax (identical in both pair warps) ----
        float tmax_lo = -1e30f, tmax_hi = -1e30f;
#pragma unroll
        for (int nt = 0; nt < 4; nt++) {
#pragma unroll
            for (int c = 0; c < 4; c++) {
                int j = j0 + nt * 8 + 2 * tig + (c & 1);
                int qi = (c < 2) ? qi_lo : qi_hi;
                float s = sc[nt][c] * (ATTN_SCALE / 50.0f);
                float e = __expf(2.0f * s);
                s = 50.0f * (1.0f - __fdividef(2.0f, e + 1.0f));
                bool valid = (j <= qi) && ((qi - j) < SWIN);
                s = valid ? s : -1e30f;
                sc[nt][c] = s;
                if (c < 2) tmax_lo = fmaxf(tmax_lo, s); else tmax_hi = fmaxf(tmax_hi, s);
            }
        }
        tmax_lo = fmaxf(tmax_lo, __shfl_xor_sync(0xffffffffu, tmax_lo, 1));
        tmax_lo = fmaxf(tmax_lo, __shfl_xor_sync(0xffffffffu, tmax_lo, 2));
        tmax_hi = fmaxf(tmax_hi, __shfl_xor_sync(0xffffffffu, tmax_hi, 1));
        tmax_hi = fmaxf(tmax_hi, __shfl_xor_sync(0xffffffffu, tmax_hi, 2));
        float mn_lo = fmaxf(m_lo, tmax_lo), mn_hi = fmaxf(m_hi, tmax_hi);
        float al = __expf(m_lo - mn_lo), ah = __expf(m_hi - mn_hi);
        m_lo = mn_lo; m_hi = mn_hi;

        float ps_lo = 0.f, ps_hi = 0.f;
#pragma unroll
        for (int nt = 0; nt < 4; nt++) {
#pragma unroll
            for (int c = 0; c < 4; c++) {
                float s = sc[nt][c];
                float mm = (c < 2) ? m_lo : m_hi;
                float pv = (s > -1e29f) ? __expf(s - mm) : 0.f;
                sc[nt][c] = pv;
                if (c < 2) ps_lo += pv; else ps_hi += pv;
            }
        }
        l_lo = l_lo * al + ps_lo;
        l_hi = l_hi * ah + ps_hi;
#pragma unroll
        for (int nt = 0; nt < 16; nt++) {
            o[nt][0] *= al; o[nt][1] *= al; o[nt][2] *= ah; o[nt][3] *= ah;
        }

        // ---- PV over this warp's half of output HD ----
        const int src0 = (lane & ~3) | (tig >> 1);
        const int src1 = src0 + 2;
#pragma unroll
        for (int kk = 0; kk < 4; kk++) {
            float s0 = __shfl_sync(0xffffffffu, sc[kk][0], src0);
            float s1 = __shfl_sync(0xffffffffu, sc[kk][1], src0);
            float s2 = __shfl_sync(0xffffffffu, sc[kk][2], src0);
            float s3 = __shfl_sync(0xffffffffu, sc[kk][3], src0);
            float u0 = __shfl_sync(0xffffffffu, sc[kk][0], src1);
            float u1 = __shfl_sync(0xffffffffu, sc[kk][1], src1);
            float u2 = __shfl_sync(0xffffffffu, sc[kk][2], src1);
            float u3 = __shfl_sync(0xffffffffu, sc[kk][3], src1);
            unsigned a0 = f2tf((tig & 1) ? s1 : s0);
            unsigned a1 = f2tf((tig & 1) ? s3 : s2);
            unsigned a2 = f2tf((tig & 1) ? u1 : u0);
            unsigned a3 = f2tf((tig & 1) ? u3 : u2);
#pragma unroll
            for (int p = 0; p < 8; p++) {
                int pg = half * 8 + p;
                unsigned v0, v1, v2, v3;
                ldsm4(v0, v1, v2, v3, sv + (unsigned)(((pg * 16 + lrow) * AVP + kk * 8 + lcol) * 4));
                mma_tf32(o[2*p][0],   o[2*p][1],   o[2*p][2],   o[2*p][3],   a0, a1, a2, a3, v0, v1);
                mma_tf32(o[2*p+1][0], o[2*p+1][1], o[2*p+1][2], o[2*p+1][3], a0, a1, a2, a3, v2, v3);
            }
        }
    }

    l_lo += __shfl_xor_sync(0xffffffffu, l_lo, 1);
    l_lo += __shfl_xor_sync(0xffffffffu, l_lo, 2);
    l_hi += __shfl_xor_sync(0xffffffffu, l_hi, 1);
    l_hi += __shfl_xor_sync(0xffffffffu, l_hi, 2);
    float inv_lo = 1.0f / l_lo, inv_hi = 1.0f / l_hi;
#pragma unroll
    for (int nt = 0; nt < 16; nt++) {
        int col = h * HD + (half * 16 + nt) * 8 + 2 * tig;
        float2 lo = make_float2(__uint_as_float(f2tf(o[nt][0] * inv_lo)), __uint_as_float(f2tf(o[nt][1] * inv_lo)));
        float2 hi = make_float2(__uint_as_float(f2tf(o[nt][2] * inv_hi)), __uint_as_float(f2tf(o[nt][3] * inv_hi)));
        *(float2*)&out[(size_t)qi_lo * QDIM + col] = lo;
        *(float2*)&out[(size_t)qi_hi * QDIM + col] = hi;
    }
}

extern "C" void kernel_launch(void* const* d_in, const int* in_sizes, int n_in,
                              void* d_out, int out_size) {
    const float* x   = (const float*)d_in[0];
    const int*   pos = (const int*)  d_in[1];
    const float* Wq  = (const float*)d_in[2];
    const float* Wk  = (const float*)d_in[3];
    const float* Wv  = (const float*)d_in[4];
    const float* Wo  = (const float*)d_in[5];
    float* out = (float*)d_out;

    float *ao, *rx, *rwo;
    cudaGetSymbolAddress((void**)&ao,  g_ao);
    cudaGetSymbolAddress((void**)&rx,  g_x);
    cudaGetSymbolAddress((void**)&rwo, g_wo);   // FIXED: device symbol address, not host symbol

    int gsm = 6 * 128 * GKP * 4;   // 3 stages x (A+B)
    cudaFuncSetAttribute(gemm3<1>, cudaFuncAttributeMaxDynamicSharedMemorySize, gsm);
    cudaFuncSetAttribute(gemm3<0>, cudaFuncAttributeMaxDynamicSharedMemorySize, gsm);
    int asm_ = (SXOFF + 8 * 512) * 4;
    cudaFuncSetAttribute(attn_tc, cudaFuncAttributeMaxDynamicSharedMemorySize, asm_);

    // launches ordered so gemm3<1> is the 4th launch (ncu profiles the 4th)
    round_copy<<<4608, 256>>>(rx, x, 1179648);                       // x first half
    round_copy<<<4608, 256>>>(rx + 4718592, x + 4718592, 1179648);   // x second half
    round_w4<<<13824, 256>>>(Wq, Wk, Wv, Wo);
    gemm3<1><<<dim3(4096/128, S_LEN/128), 128, gsm>>>(rx, nullptr, nullptr, 4096, HID);
    rope_kernel<<<S_LEN, 256>>>(pos);
    transpose_round_v<<<dim3(S_LEN/32, KVDIM/32), 256>>>();
    attn_tc<<<dim3(S_LEN/BQ, NH), 256, asm_>>>(ao);
    gemm3<0><<<dim3(HID/128, S_LEN/128), 128, gsm>>>(ao, rwo, out, HID, QDIM);
}

// round 12
// speedup vs baseline: 1.1252x; 1.1252x over previous
#include <cuda_runtime.h>
#include <math.h>

#define S_LEN 4096
#define HID 2304
#define NH 8
#define NKV 4
#define HD 256
#define QDIM 2048
#define KVDIM 1024
#define SWIN 2048
#define ATTN_SCALE 0.0625f

__device__ float g_q [S_LEN*QDIM];
__device__ float g_k [S_LEN*KVDIM];
__device__ float g_v [S_LEN*KVDIM];
__device__ float g_vt[KVDIM*S_LEN];
__device__ float g_ao[S_LEN*QDIM];
__device__ float g_x [S_LEN*HID];
__device__ float g_wq[QDIM*HID];
__device__ float g_wk[KVDIM*HID];
__device__ float g_wv[KVDIM*HID];
__device__ float g_wo[HID*QDIM];

__device__ __forceinline__ unsigned f2tf(float f) {
    unsigned u; asm("cvt.rna.tf32.f32 %0, %1;" : "=r"(u) : "f"(f)); return u;
}
__device__ __forceinline__ unsigned s2u(const void* p) {
    return (unsigned)__cvta_generic_to_shared(p);
}
__device__ __forceinline__ void ldsm4(unsigned& r0, unsigned& r1, unsigned& r2, unsigned& r3, unsigned a) {
    asm volatile("ldmatrix.sync.aligned.m8n8.x4.shared.b16 {%0,%1,%2,%3},[%4];"
                 : "=r"(r0), "=r"(r1), "=r"(r2), "=r"(r3) : "r"(a));
}
__device__ __forceinline__ void cpa16(unsigned d, const float* s) {
    asm volatile("cp.async.cg.shared.global [%0],[%1],16;" :: "r"(d), "l"(s));
}
#define CP_COMMIT() asm volatile("cp.async.commit_group;")
#define CP_WAIT0()  asm volatile("cp.async.wait_group 0;")
#define CP_WAIT1()  asm volatile("cp.async.wait_group 1;")

__device__ __forceinline__ void mma_tf32(float& c0, float& c1, float& c2, float& c3,
        unsigned a0, unsigned a1, unsigned a2, unsigned a3, unsigned b0, unsigned b1) {
    asm volatile("mma.sync.aligned.m16n8k8.row.col.f32.tf32.tf32.f32 "
        "{%0,%1,%2,%3},{%4,%5,%6,%7},{%8,%9},{%0,%1,%2,%3};\n"
        : "+f"(c0), "+f"(c1), "+f"(c2), "+f"(c3)
        : "r"(a0), "r"(a1), "r"(a2), "r"(a3), "r"(b0), "r"(b1));
}

__global__ __launch_bounds__(256) void round_copy(float* __restrict__ d, const float* __restrict__ s, int n4) {
    int i = blockIdx.x * 256 + threadIdx.x;
    if (i < n4) {
        float4 v = ((const float4*)s)[i];
        ((uint4*)d)[i] = make_uint4(f2tf(v.x), f2tf(v.y), f2tf(v.z), f2tf(v.w));
    }
}

// wq: 1179648 f4, wk/wv: 589824 f4 each, wo: 1179648 f4. total 3538944 f4.
__global__ __launch_bounds__(256) void round_w4(const float* __restrict__ wq,
        const float* __restrict__ wk, const float* __restrict__ wv,
        const float* __restrict__ wo) {
    int i = blockIdx.x * 256 + threadIdx.x;
    const float* s; float* d; int off;
    if (i < 1179648)      { s = wq; d = g_wq; off = i; }
    else if (i < 1769472) { s = wk; d = g_wk; off = i - 1179648; }
    else if (i < 2359296) { s = wv; d = g_wv; off = i - 1769472; }
    else                  { s = wo; d = g_wo; off = i - 2359296; }
    float4 v = ((const float4*)s)[off];
    ((uint4*)d)[off] = make_uint4(f2tf(v.x), f2tf(v.y), f2tf(v.z), f2tf(v.w));
}

__global__ __launch_bounds__(256) void transpose_round_v() {
    __shared__ float tile[32][33];
    int s0 = blockIdx.x * 32, d0 = blockIdx.y * 32;
    int tx = threadIdx.x & 31, ty = threadIdx.x >> 5;
#pragma unroll
    for (int i = 0; i < 4; i++)
        tile[ty + 8*i][tx] = g_v[(size_t)(s0 + ty + 8*i) * KVDIM + d0 + tx];
    __syncthreads();
#pragma unroll
    for (int i = 0; i < 4; i++)
        g_vt[(size_t)(d0 + ty + 8*i) * S_LEN + s0 + tx] = __uint_as_float(f2tf(tile[tx][ty + 8*i]));
}

__global__ __launch_bounds__(256) void rope_kernel(const int* __restrict__ pos) {
    __shared__ float cs[128], sn[128];
    const int s = blockIdx.x, t = threadIdx.x;
    const float p = (float)pos[s];
    if (t < 128) {
        float invf = 1.0f / powf(10000.0f, (float)(2 * t) / 256.0f);
        sincosf(p * invf, &sn[t], &cs[t]);
    }
    __syncthreads();
    for (int idx = t; idx < (NH + NKV) * 128; idx += 256) {
        int h = idx >> 7, d = idx & 127;
        float c = cs[d], ss = sn[d];
        float* b = (h < NH) ? (g_q + (size_t)s * QDIM + h * HD)
                            : (g_k + (size_t)s * KVDIM + (h - NH) * HD);
        float x1 = b[d], x2 = b[d + 128];
        b[d]       = __uint_as_float(f2tf(x1 * c - x2 * ss));
        b[d + 128] = __uint_as_float(f2tf(x2 * c + x1 * ss));
    }
}

// ---------- GEMM: 256 thr, 128x128 tile, 8 warps x 64x32, 3-stage cp.async --
#define GKP 36
__device__ __forceinline__ void g3_issue(unsigned sa, unsigned sb,
        const float* __restrict__ A, const float* __restrict__ B,
        int m0, int bn0, int K, int k0, int r0w, int cw) {
#pragma unroll
    for (int i = 0; i < 4; i++) {
        int r = r0w + 32 * i;
        cpa16(sa + (unsigned)((r * GKP + cw) * 4), A + (size_t)(m0 + r) * K + k0 + cw);
        cpa16(sb + (unsigned)((r * GKP + cw) * 4), B + (size_t)(bn0 + r) * K + k0 + cw);
    }
    CP_COMMIT();
}

// QKV==1: fused projection with output routing; QKV==0: plain C=A*B^T
template<int QKV>
__global__ __launch_bounds__(256, 2) void gemm3(const float* __restrict__ A,
        const float* __restrict__ B_, float* __restrict__ C_, int N, int K) {
    extern __shared__ float smf[];
    const int t = threadIdx.x, lane = t & 31, wid = t >> 5;
    const int g = lane >> 2, tig = lane & 3;
    const int wm = (wid >> 2) * 64, wn = (wid & 3) * 32;   // 2x4 warp grid
    const int m0 = blockIdx.y * 128, n0 = blockIdx.x * 128;
    const unsigned sb0 = s2u(smf);
    const unsigned STG = 128u * GKP * 4u;
    const int r0w = t >> 3, cw = (t & 7) * 4;
    const int lrow = (lane & 7) + ((lane >> 4) & 1) * 8;
    const int lcol = ((lane >> 3) & 1) * 4;

    const float* B; float* C; int bn0, Nld;
    if (QKV) {
        if (n0 < 2048)      { B = g_wq; C = g_q; bn0 = n0;        Nld = 2048; }
        else if (n0 < 3072) { B = g_wk; C = g_k; bn0 = n0 - 2048; Nld = 1024; }
        else                { B = g_wv; C = g_v; bn0 = n0 - 3072; Nld = 1024; }
    } else { B = B_; C = C_; bn0 = n0; Nld = N; }

    float acc[4][4][4];   // [mt16][nt8][frag]
#pragma unroll
    for (int mt = 0; mt < 4; mt++)
#pragma unroll
        for (int nt = 0; nt < 4; nt++)
#pragma unroll
            for (int c = 0; c < 4; c++) acc[mt][nt][c] = 0.f;

    const int nch = K >> 5;
    g3_issue(sb0, sb0 + 3u*STG, A, B, m0, bn0, K, 0, r0w, cw);
    g3_issue(sb0 + STG, sb0 + 4u*STG, A, B, m0, bn0, K, 32, r0w, cw);
    for (int ci = 0; ci < nch; ci++) {
        if (ci + 1 < nch) { CP_WAIT1(); } else { CP_WAIT0(); }
        __syncthreads();
        if (ci + 2 < nch) {
            int s = (ci + 2) % 3;
            g3_issue(sb0 + (unsigned)s*STG, sb0 + (unsigned)(s+3)*STG, A, B, m0, bn0, K, (ci + 2) << 5, r0w, cw);
        }
        const unsigned sa = sb0 + (unsigned)(ci % 3) * STG;
        const unsigned sbb = sb0 + (unsigned)(ci % 3 + 3) * STG;
#pragma unroll
        for (int ks = 0; ks < 32; ks += 8) {
            unsigned a[4][4], b[2][4];
#pragma unroll
            for (int mt = 0; mt < 4; mt++)
                ldsm4(a[mt][0], a[mt][1], a[mt][2], a[mt][3],
                      sa + (unsigned)(((wm + mt*16 + lrow) * GKP + ks + lcol) * 4));
#pragma unroll
            for (int p = 0; p < 2; p++)
                ldsm4(b[p][0], b[p][1], b[p][2], b[p][3],
                      sbb + (unsigned)(((wn + p*16 + lrow) * GKP + ks + lcol) * 4));
#pragma unroll
            for (int nt = 0; nt < 4; nt++) {
                unsigned b0 = b[nt >> 1][(nt & 1) * 2], b1 = b[nt >> 1][(nt & 1) * 2 + 1];
#pragma unroll
                for (int mt = 0; mt < 4; mt++)
                    mma_tf32(acc[mt][nt][0], acc[mt][nt][1], acc[mt][nt][2], acc[mt][nt][3],
                             a[mt][0], a[mt][2], a[mt][1], a[mt][3], b0, b1);
            }
        }
    }
#pragma unroll
    for (int mt = 0; mt < 4; mt++) {
        int row = m0 + wm + mt * 16 + g;
#pragma unroll
        for (int nt = 0; nt < 4; nt++) {
            int col = bn0 + wn + nt * 8 + 2 * tig;
            *(float2*)&C[(size_t)row * Nld + col]       = make_float2(acc[mt][nt][0], acc[mt][nt][1]);
            *(float2*)&C[(size_t)(row + 8) * Nld + col] = make_float2(acc[mt][nt][2], acc[mt][nt][3]);
        }
    }
}

// ---------------- Flash attention (round-8 version) -------------------------
#define BQ 64
#define BK 32
#define AQP 260
#define AVP 36
#define SXOFF (64*AQP + 2*32*AQP + 2*256*AVP)   // 51712 words

__device__ __forceinline__ void attn_issue(unsigned sk, unsigned sv, int j0, int hkv, int t) {
#pragma unroll
    for (int i = 0; i < 8; i++) {
        int c = t + 256 * i;
        int r = c >> 6, col = (c & 63) * 4;
        cpa16(sk + (unsigned)((r * AQP + col) * 4), g_k + (size_t)(j0 + r) * KVDIM + hkv * HD + col);
    }
#pragma unroll
    for (int i = 0; i < 8; i++) {
        int c = t + 256 * i;
        int r = c >> 3, col = (c & 7) * 4;
        cpa16(sv + (unsigned)((r * AVP + col) * 4), g_vt + (size_t)(hkv * HD + r) * S_LEN + j0 + col);
    }
    CP_COMMIT();
}

__global__ __launch_bounds__(256, 1) void attn_tc(float* __restrict__ out) {
    extern __shared__ float smf[];
    const unsigned sb0 = s2u(smf);
    const unsigned sQ  = sb0;
    const unsigned sK0 = sb0 + 64u*AQP*4u, sK1 = sK0 + 32u*AQP*4u;
    const unsigned sV0 = sK1 + 32u*AQP*4u, sV1 = sV0 + 256u*AVP*4u;
    float* Qs = smf;
    float* Sx = smf + SXOFF;

    const int t = threadIdx.x, lane = t & 31, wid = t >> 5;
    const int g = lane >> 2, tig = lane & 3;
    const int pairid = wid & 3, half = wid >> 2;
    const int h = blockIdx.y;
    const int q0 = (int)(gridDim.x - 1 - blockIdx.x) * BQ;
    const int hkv = h >> 1;
    const int rbase = pairid * 16;
    const int ksbase = half * 128;
    const int qi_lo = q0 + rbase + g, qi_hi = qi_lo + 8;
    const int lrow = (lane & 7) + ((lane >> 4) & 1) * 8;
    const int lcol = ((lane >> 3) & 1) * 4;
    float* myS   = Sx + wid * 512;
    float* peerS = Sx + (wid ^ 4) * 512;

    int jlo = q0 - (SWIN - 1); if (jlo < 0) jlo = 0;
    const int jstart = jlo & ~(BK - 1);
    const int ntiles = (q0 + BQ - jstart) / BK;

    attn_issue(sK0, sV0, jstart, hkv, t);
    for (int i = t; i < 64 * 64; i += 256) {
        int r = i >> 6, c = (i & 63) * 4;
        *(float4*)&Qs[r * AQP + c] = *(const float4*)&g_q[(size_t)(q0 + r) * QDIM + h * HD + c];
    }

    float o[16][4];
#pragma unroll
    for (int nt = 0; nt < 16; nt++)
#pragma unroll
        for (int c = 0; c < 4; c++) o[nt][c] = 0.f;
    float m_lo = -1e30f, m_hi = -1e30f, l_lo = 0.f, l_hi = 0.f;

    for (int ci = 0; ci < ntiles; ci++) {
        const int j0 = jstart + ci * BK;
        CP_WAIT0();
        __syncthreads();
        if (ci + 1 < ntiles)
            attn_issue((ci & 1) ? sK0 : sK1, (ci & 1) ? sV0 : sV1, j0 + BK, hkv, t);
        const unsigned sk = (ci & 1) ? sK1 : sK0;
        const unsigned sv = (ci & 1) ? sV1 : sV0;

        float sc[4][4];
#pragma unroll
        for (int nt = 0; nt < 4; nt++)
#pragma unroll
            for (int c = 0; c < 4; c++) sc[nt][c] = 0.f;
#pragma unroll 4
        for (int ksi = 0; ksi < 16; ksi++) {
            unsigned qa0, qa1, qa2, qa3;
            ldsm4(qa0, qa1, qa2, qa3, sQ + (unsigned)(((rbase + lrow) * AQP + ksbase + ksi * 8 + lcol) * 4));
            unsigned kb[2][4];
#pragma unroll
            for (int p = 0; p < 2; p++)
                ldsm4(kb[p][0], kb[p][1], kb[p][2], kb[p][3],
                      sk + (unsigned)(((p * 16 + lrow) * AQP + ksbase + ksi * 8 + lcol) * 4));
#pragma unroll
            for (int nt = 0; nt < 4; nt++) {
                unsigned b0 = kb[nt >> 1][(nt & 1) * 2], b1 = kb[nt >> 1][(nt & 1) * 2 + 1];
                mma_tf32(sc[nt][0], sc[nt][1], sc[nt][2], sc[nt][3], qa0, qa2, qa1, qa3, b0, b1);
            }
        }

#pragma unroll
        for (int nt = 0; nt < 4; nt++)
#pragma unroll
            for (int c = 0; c < 4; c++)
                myS[(nt * 4 + c) * 32 + lane] = sc[nt][c];
        __syncthreads();
#pragma unroll
        for (int nt = 0; nt < 4; nt++)
#pragma unroll
            for (int c = 0; c < 4; c++)
                sc[nt][c] += peerS[(nt * 4 + c) * 32 + lane];

        float tmax_lo = -1e30f, tmax_hi = -1e30f;
#pragma unroll
        for (int nt = 0; nt < 4; nt++) {
#pragma unroll
            for (int c = 0; c < 4; c++) {
                int j = j0 + nt * 8 + 2 * tig + (c & 1);
                int qi = (c < 2) ? qi_lo : qi_hi;
                float s = sc[nt][c] * (ATTN_SCALE / 50.0f);
                float e = __expf(2.0f * s);
                s = 50.0f * (1.0f - __fdividef(2.0f, e + 1.0f));
                bool valid = (j <= qi) && ((qi - j) < SWIN);
                s = valid ? s : -1e30f;
                sc[nt][c] = s;
                if (c < 2) tmax_lo = fmaxf(tmax_lo, s); else tmax_hi = fmaxf(tmax_hi, s);
            }
        }
        tmax_lo = fmaxf(tmax_lo, __shfl_xor_sync(0xffffffffu, tmax_lo, 1));
        tmax_lo = fmaxf(tmax_lo, __shfl_xor_sync(0xffffffffu, tmax_lo, 2));
        tmax_hi = fmaxf(tmax_hi, __shfl_xor_sync(0xffffffffu, tmax_hi, 1));
        tmax_hi = fmaxf(tmax_hi, __shfl_xor_sync(0xffffffffu, tmax_hi, 2));
        float mn_lo = fmaxf(m_lo, tmax_lo), mn_hi = fmaxf(m_hi, tmax_hi);
        float al = __expf(m_lo - mn_lo), ah = __expf(m_hi - mn_hi);
        m_lo = mn_lo; m_hi = mn_hi;

        float ps_lo = 0.f, ps_hi = 0.f;
#pragma unroll
        for (int nt = 0; nt < 4; nt++) {
#pragma unroll
            for (int c = 0; c < 4; c++) {
                float s = sc[nt][c];
                float mm = (c < 2) ? m_lo : m_hi;
                float pv = (s > -1e29f) ? __expf(s - mm) : 0.f;
                sc[nt][c] = pv;
                if (c < 2) ps_lo += pv; else ps_hi += pv;
            }
        }
        l_lo = l_lo * al + ps_lo;
        l_hi = l_hi * ah + ps_hi;
#pragma unroll
        for (int nt = 0; nt < 16; nt++) {
            o[nt][0] *= al; o[nt][1] *= al; o[nt][2] *= ah; o[nt][3] *= ah;
        }

        const int src0 = (lane & ~3) | (tig >> 1);
        const int src1 = src0 + 2;
#pragma unroll
        for (int kk = 0; kk < 4; kk++) {
            float s0 = __shfl_sync(0xffffffffu, sc[kk][0], src0);
            float s1 = __shfl_sync(0xffffffffu, sc[kk][1], src0);
            float s2 = __shfl_sync(0xffffffffu, sc[kk][2], src0);
            float s3 = __shfl_sync(0xffffffffu, sc[kk][3], src0);
            float u0 = __shfl_sync(0xffffffffu, sc[kk][0], src1);
            float u1 = __shfl_sync(0xffffffffu, sc[kk][1], src1);
            float u2 = __shfl_sync(0xffffffffu, sc[kk][2], src1);
            float u3 = __shfl_sync(0xffffffffu, sc[kk][3], src1);
            unsigned a0 = f2tf((tig & 1) ? s1 : s0);
            unsigned a1 = f2tf((tig & 1) ? s3 : s2);
            unsigned a2 = f2tf((tig & 1) ? u1 : u0);
            unsigned a3 = f2tf((tig & 1) ? u3 : u2);
#pragma unroll
            for (int p = 0; p < 8; p++) {
                int pg = half * 8 + p;
                unsigned v0, v1, v2, v3;
                ldsm4(v0, v1, v2, v3, sv + (unsigned)(((pg * 16 + lrow) * AVP + kk * 8 + lcol) * 4));
                mma_tf32(o[2*p][0],   o[2*p][1],   o[2*p][2],   o[2*p][3],   a0, a1, a2, a3, v0, v1);
                mma_tf32(o[2*p+1][0], o[2*p+1][1], o[2*p+1][2], o[2*p+1][3], a0, a1, a2, a3, v2, v3);
            }
        }
    }

    l_lo += __shfl_xor_sync(0xffffffffu, l_lo, 1);
    l_lo += __shfl_xor_sync(0xffffffffu, l_lo, 2);
    l_hi += __shfl_xor_sync(0xffffffffu, l_hi, 1);
    l_hi += __shfl_xor_sync(0xffffffffu, l_hi, 2);
    float inv_lo = 1.0f / l_lo, inv_hi = 1.0f / l_hi;
#pragma unroll
    for (int nt = 0; nt < 16; nt++) {
        int col = h * HD + (half * 16 + nt) * 8 + 2 * tig;
        float2 lo = make_float2(__uint_as_float(f2tf(o[nt][0] * inv_lo)), __uint_as_float(f2tf(o[nt][1] * inv_lo)));
        float2 hi = make_float2(__uint_as_float(f2tf(o[nt][2] * inv_hi)), __uint_as_float(f2tf(o[nt][3] * inv_hi)));
        *(float2*)&out[(size_t)qi_lo * QDIM + col] = lo;
        *(float2*)&out[(size_t)qi_hi * QDIM + col] = hi;
    }
}

extern "C" void kernel_launch(void* const* d_in, const int* in_sizes, int n_in,
                              void* d_out, int out_size) {
    const float* x   = (const float*)d_in[0];
    const int*   pos = (const int*)  d_in[1];
    const float* Wq  = (const float*)d_in[2];
    const float* Wk  = (const float*)d_in[3];
    const float* Wv  = (const float*)d_in[4];
    const float* Wo  = (const float*)d_in[5];
    float* out = (float*)d_out;

    float *ao, *rx, *rwo;
    cudaGetSymbolAddress((void**)&ao,  g_ao);
    cudaGetSymbolAddress((void**)&rx,  g_x);
    cudaGetSymbolAddress((void**)&rwo, g_wo);

    int gsm = 6 * 128 * GKP * 4;
    cudaFuncSetAttribute(gemm3<1>, cudaFuncAttributeMaxDynamicSharedMemorySize, gsm);
    cudaFuncSetAttribute(gemm3<0>, cudaFuncAttributeMaxDynamicSharedMemorySize, gsm);
    int asm_ = (SXOFF + 8 * 512) * 4;
    cudaFuncSetAttribute(attn_tc, cudaFuncAttributeMaxDynamicSharedMemorySize, asm_);

    // gemm3<1> stays at the 4th launch slot (profiled)
    round_copy<<<4608, 256>>>(rx, x, 1179648);
    round_copy<<<4608, 256>>>(rx + 4718592, x + 4718592, 1179648);
    round_w4<<<13824, 256>>>(Wq, Wk, Wv, Wo);
    gemm3<1><<<dim3(4096/128, S_LEN/128), 256, gsm>>>(rx, nullptr, nullptr, 4096, HID);
    rope_kernel<<<S_LEN, 256>>>(pos);
    transpose_round_v<<<dim3(S_LEN/32, KVDIM/32), 256>>>();
    attn_tc<<<dim3(S_LEN/BQ, NH), 256, asm_>>>(ao);
    gemm3<0><<<dim3(HID/128, S_LEN/128), 256, gsm>>>(ao, rwo, out, HID, QDIM);
}